// round 3
// baseline (speedup 1.0000x reference)
#include <cuda_runtime.h>

#define T_LEN 2048
#define NGRP  (T_LEN / 4)

__device__ __forceinline__ float tanh_fast(float x) {
    float y;
    asm("tanh.approx.f32 %0, %1;" : "=f"(y) : "f"(x));
    return y;
}

// State carried in the x10 domain (WU = 10*wu etc). Clips at +-1e5 dropped:
// reachable |p - et...| <= O(T) ~ 2e3 << 1e5, exact no-op.
//
// Triangular dependence (WU -> WU; WL <- WL,REM(WU); WD <- WD,X(WL)) lets the
// three sequential chains be SKEWED by one group of 4 timesteps and executed
// concurrently each iteration, hiding the per-step tanh latency chain.
__global__ void __launch_bounds__(32, 1) xaj_kernel(
    const float* __restrict__ inputs,
    const float* __restrict__ pwum, const float* __restrict__ pwlm,
    const float* __restrict__ pwdm, const float* __restrict__ pc,
    const float* __restrict__ pb,  const float* __restrict__ pk1,
    const float* __restrict__ pk2, const float* __restrict__ pk3,
    float* __restrict__ out, int B)
{
    const int b = blockIdx.x * blockDim.x + threadIdx.x;
    if (b >= B) return;

    // reference arg swap: runoff_production(wu, wd, wl, p, wum, wdm, wlm, b, c)
    const float wum_p = pwum[0] * 19.9f + 0.1f;
    const float wlm_p = pwdm[0] * 30.0f + 60.0f;
    const float wdm_p = pwlm[0] * 60.0f + 60.0f;
    const float W     = wum_p + wlm_p + wdm_p;
    const float invW10 = 0.1f / W;          // x10-state -> w/W
    const float c2 = pc[0] * 0.19f + 0.01f;
    const float b2 = pb[0] * 0.30f + 0.10f;
    const float k1 = pk1[0] * 0.69f + 0.01f;
    const float k2 = pk2[0] * 0.69f + 0.01f;
    const float k3 = pk3[0] * 0.89f + 0.01f;
    const float F = k1 + 0.5f * k2 * (1.0f - k1)
                  + 0.25f * k3 * (1.0f - k2) * (1.0f - k1);
    const float halfF = 0.5f * F;

    const float4* __restrict__ in4 =
        reinterpret_cast<const float4*>(inputs + (size_t)b * (T_LEN * 3));
    float4* __restrict__ out4 =
        reinterpret_cast<float4*>(out + (size_t)b * T_LEN);

    float WU = 0.0f, WL = 0.0f, WD = 0.0f;

    // pipeline buffers (zero-init => warm-up iterations are exact no-ops:
    // ET2 = ET3 = 0, D = 0, states stay 0)
    float REMb[4] = {0,0,0,0}, D1b[4] = {0,0,0,0}, T3b[4] = {0,0,0,0};
    float Xb[4]   = {0,0,0,0}, D2b[4] = {0,0,0,0}, T5b[4] = {0,0,0,0};
    float WUa[4]  = {0,0,0,0}, WUc[4] = {0,0,0,0};
    float Pa[4]   = {0,0,0,0}, Pc[4]  = {0,0,0,0};

    // held input group (prefetched one iteration ahead)
    float4 A = in4[0], Bv = in4[1], C = in4[2];

    for (int g = 0; g < NGRP + 2; ++g) {
        // prefetch group g+1 (clamped; tail garbage never reaches output)
        const int gn = (g + 1 < NGRP) ? (g + 1) : (NGRP - 1);
        const float4 nA = in4[gn * 3 + 0];
        const float4 nB = in4[gn * 3 + 1];
        const float4 nC = in4[gn * 3 + 2];

        // (B,T,3): pet = ch0, p = ch2
        const float pet_[4] = { A.x, A.w, Bv.z, C.y };
        const float pr_[4]  = { A.z, Bv.y, C.x, C.w };

        // ---- stage A: WU chain + REM for group g ----
        float nREM[4], nD1[4], nT3[4], nWU[4];
        #pragma unroll
        for (int i = 0; i < 4; ++i) {
            const float pet10 = 10.0f * pet_[i];
            const float p10   = 10.0f * pr_[i];
            const float t1  = tanh_fast(WU - pet10);
            const float ET1 = fmaf(t1, 0.5f * (pet10 - WU), 0.5f * (pet10 + WU));
            const float Z   = pet10 - ET1;
            const float tr  = tanh_fast(Z);
            const float hZ  = 0.5f * Z;
            const float REM = fmaf(tr, hZ, hZ);
            const float D1  = p10 - ET1;
            WU += D1;
            nREM[i] = REM;
            nD1[i]  = D1;
            nT3[i]  = tanh_fast(REM);   // gate H(rem), hoisted off WL chain
            nWU[i]  = WU;
        }

        // ---- stage B: WL chain + X for group g-1 ----
        float nX[4], nD2[4], nT5[4];
        #pragma unroll
        for (int i = 0; i < 4; ++i) {
            const float REM  = REMb[i];
            const float t2   = tanh_fast(REM - WL);
            const float ET22 = fmaf(t2, 0.5f * (WL - REM), 0.5f * (WL + REM));
            const float hE   = 0.5f * ET22;
            const float ET2  = fmaf(T3b[i], hE, hE);
            const float D2   = D1b[i] - ET2;
            WL += D2;
            const float X = REM - ET2;
            nX[i]  = X;
            nD2[i] = D2;
            nT5[i] = tanh_fast(X);      // gate H(x), hoisted off WD chain
        }

        // ---- stage C: WD chain + runoff/q for group g-2 ----
        float qv[4];
        #pragma unroll
        for (int i = 0; i < 4; ++i) {
            const float X    = Xb[i];
            const float t4   = tanh_fast(X - WD);
            const float ET33 = fmaf(t4, 0.5f * (WD - X), 0.5f * (WD + X));
            const float hE   = 0.5f * ET33;
            const float ET3  = fmaf(T5b[i], hE, hE);
            WD += D2b[i] - ET3;

            // runoff_production(wu, wd, wl, ...): u uses wu, v uses wd
            const float u  = WUc[i] * invW10;
            const float v  = WD * invW10;
            const float s  = fmaf(c2, u * u, b2 * (v * v));
            const float dd = Pc[i] - s;
            const float tq = tanh_fast(10.0f * dd);
            const float qh = halfF * dd;
            qv[i] = fmaf(tq, qh, qh);   // F * H(p-s) * (p-s)
        }

        if (g >= 2)
            out4[g - 2] = make_float4(qv[0], qv[1], qv[2], qv[3]);

        // ---- rotate pipeline buffers ----
        #pragma unroll
        for (int i = 0; i < 4; ++i) {
            Xb[i]   = nX[i];  D2b[i] = nD2[i]; T5b[i] = nT5[i];
            WUc[i]  = WUa[i]; Pc[i]  = Pa[i];
            WUa[i]  = nWU[i]; Pa[i]  = pr_[i];
            REMb[i] = nREM[i]; D1b[i] = nD1[i]; T3b[i] = nT3[i];
        }

        A = nA; Bv = nB; C = nC;
    }
}

extern "C" void kernel_launch(void* const* d_in, const int* in_sizes, int n_in,
                              void* d_out, int out_size) {
    const float* inputs = (const float*)d_in[0];
    const float* wum = (const float*)d_in[1];
    const float* wlm = (const float*)d_in[2];
    const float* wdm = (const float*)d_in[3];
    const float* c   = (const float*)d_in[4];
    const float* bb  = (const float*)d_in[5];
    const float* k1  = (const float*)d_in[6];
    const float* k2  = (const float*)d_in[7];
    const float* k3  = (const float*)d_in[8];
    float* out = (float*)d_out;

    const int B = in_sizes[0] / (T_LEN * 3);

    dim3 block(32);
    dim3 grid((B + 31) / 32);
    xaj_kernel<<<grid, block>>>(inputs, wum, wlm, wdm, c, bb, k1, k2, k3, out, B);
}

// round 4
// speedup vs baseline: 1.3988x; 1.3988x over previous
#include <cuda_runtime.h>

#define T_LEN   2048
#define CSTEP   32                      // timesteps per chunk
#define NCHUNK  (T_LEN / CSTEP)         // 64
#define NITER   (NCHUNK + 2)            // pipeline depth 3
#define NGRP_C  (CSTEP / 4)             // float4-groups per chunk

__device__ __forceinline__ float tanh_fast(float x) {
    float y;
    asm("tanh.approx.f32 %0, %1;" : "=f"(y) : "f"(x));
    return y;
}

// State carried in the x10 domain (WU = 10*wu etc); clips at +-1e5 are exact
// no-ops on reachable values (|state| <= O(T) ~ 2e3).
//
// 3-warp pipeline over the triangular dependence:
//   warp0 (A): WU chain  -> REM, D1, ct2 = p - c2*(wu/W)^2
//   warp1 (B): WL chain  -> X, D2
//   warp2 (C): WD chain  -> q, global stores
// Chunks of CSTEP steps flow A->B->C through smem; one __syncthreads per
// iteration; A/B/C work on chunks k, k-1, k-2 so all three SMSPs run their
// serial chains CONCURRENTLY (hardware-enforced, not scheduler-dependent).
__global__ void __launch_bounds__(96, 1) xaj_kernel(
    const float* __restrict__ inputs,
    const float* __restrict__ pwum, const float* __restrict__ pwlm,
    const float* __restrict__ pwdm, const float* __restrict__ pc,
    const float* __restrict__ pb,  const float* __restrict__ pk1,
    const float* __restrict__ pk2, const float* __restrict__ pk3,
    float* __restrict__ out, int B)
{
    __shared__ float sREM[2][CSTEP][32];
    __shared__ float sD1 [2][CSTEP][32];
    __shared__ float sX  [2][CSTEP][32];
    __shared__ float sD2 [2][CSTEP][32];
    __shared__ float sCT [3][CSTEP][32];   // ct2 travels A -> C (2-chunk skew)

    const int lane = threadIdx.x & 31;
    const int wid  = threadIdx.x >> 5;
    const int row  = blockIdx.x * 32 + lane;
    if (row >= B) return;   // B is a multiple of 32; never taken, keeps it safe

    // scalar params (reference arg swap: runoff_production(wu, wd, wl, p,
    // wum, wdm, wlm, b, c))
    const float wum_p = pwum[0] * 19.9f + 0.1f;
    const float wlm_p = pwdm[0] * 30.0f + 60.0f;
    const float wdm_p = pwlm[0] * 60.0f + 60.0f;
    const float W      = wum_p + wlm_p + wdm_p;
    const float invW10 = 0.1f / W;           // x10-state -> w/W
    const float negc2  = -(pc[0] * 0.19f + 0.01f);
    const float negb2  = -(pb[0] * 0.30f + 0.10f);
    const float k1 = pk1[0] * 0.69f + 0.01f;
    const float k2 = pk2[0] * 0.69f + 0.01f;
    const float k3 = pk3[0] * 0.89f + 0.01f;
    const float F  = k1 + 0.5f * k2 * (1.0f - k1)
                   + 0.25f * k3 * (1.0f - k2) * (1.0f - k1);
    const float halfF = 0.5f * F;

    const float4* __restrict__ in4 =
        reinterpret_cast<const float4*>(inputs + (size_t)row * (T_LEN * 3));
    float4* __restrict__ out4 =
        reinterpret_cast<float4*>(out + (size_t)row * T_LEN);

    float WU = 0.0f, WL = 0.0f, WD = 0.0f;

    // stage-A prefetch registers (group-level, distance 1)
    float4 A0, A1, A2;
    if (wid == 0) { A0 = in4[0]; A1 = in4[1]; A2 = in4[2]; }

    for (int k = 0; k < NITER; ++k) {
        if (wid == 0) {
            if (k < NCHUNK) {
                const int slot = k & 1, cslot = k % 3;
                #pragma unroll 2
                for (int j = 0; j < NGRP_C; ++j) {
                    const int gg = k * NGRP_C + j;
                    const int gn = (gg + 1 < T_LEN / 4) ? gg + 1 : gg;
                    const float4 N0 = in4[gn * 3 + 0];
                    const float4 N1 = in4[gn * 3 + 1];
                    const float4 N2 = in4[gn * 3 + 2];
                    // (B,T,3): pet = ch0, p = ch2
                    const float pet_[4] = { A0.x, A0.w, A1.z, A2.y };
                    const float pr_ [4] = { A0.z, A1.y, A2.x, A2.w };
                    #pragma unroll
                    for (int i = 0; i < 4; ++i) {
                        const int   t     = j * 4 + i;
                        const float pet10 = 10.0f * pet_[i];
                        const float p10   = 10.0f * pr_[i];
                        const float a    = WU - pet10;
                        const float ha   = 0.5f * a;
                        const float ct   = fmaf(-0.5f, pet10, p10);
                        const float base = fmaf(0.5f, WU, ct);
                        const float sum  = WU + p10;
                        const float t1   = tanh_fast(a);
                        const float WUn  = fmaf(t1, ha, base);   // chain: 24cyc
                        const float ET1  = sum - WUn;            // off-chain
                        const float Z    = pet10 - ET1;
                        const float tr   = tanh_fast(Z);
                        const float hZ   = 0.5f * Z;
                        const float REM  = fmaf(tr, hZ, hZ);
                        const float D1   = p10 - ET1;
                        const float u    = WUn * invW10;         // wu/W (new)
                        const float cu   = negc2 * u;
                        const float ct2  = fmaf(cu, u, pr_[i]);  // p - c2*u^2
                        sREM[slot][t][lane] = REM;
                        sD1 [slot][t][lane] = D1;
                        sCT [cslot][t][lane] = ct2;
                        WU = WUn;
                    }
                    A0 = N0; A1 = N1; A2 = N2;
                }
            }
        } else if (wid == 1) {
            if (k >= 1 && k <= NCHUNK) {
                const int kb = k - 1, slot = kb & 1;
                #pragma unroll 4
                for (int t = 0; t < CSTEP; ++t) {
                    const float REM  = sREM[slot][t][lane];
                    const float D1   = sD1 [slot][t][lane];
                    const float t3   = tanh_fast(REM);           // gate H(rem)
                    const float g3   = fmaf(t3,  0.5f,  0.5f);
                    const float ng3  = fmaf(t3, -0.5f, -0.5f);
                    const float aB   = REM - WL;
                    const float t2   = tanh_fast(aB);
                    const float hB   = -0.5f * aB;               // 0.5(WL-REM)
                    const float mB   = fmaf(0.5f, WL, 0.5f * REM);
                    const float ET22 = fmaf(t2, hB, mB);         // chain: 28cyc
                    const float ET2  = g3 * ET22;
                    const float WLD  = WL + D1;
                    WL = fmaf(ng3, ET22, WLD);                   // WL + D1 - ET2
                    sX [slot][t][lane] = REM - ET2;
                    sD2[slot][t][lane] = D1  - ET2;
                }
            }
        } else {
            if (k >= 2) {
                const int kc = k - 2, slot = kc & 1, cslot = kc % 3;
                #pragma unroll 2
                for (int j = 0; j < NGRP_C; ++j) {
                    float qv[4];
                    #pragma unroll
                    for (int i = 0; i < 4; ++i) {
                        const int   t    = j * 4 + i;
                        const float X    = sX [slot][t][lane];
                        const float D2   = sD2[slot][t][lane];
                        const float ct2  = sCT[cslot][t][lane];
                        const float t5   = tanh_fast(X);         // gate H(x)
                        const float ng5  = fmaf(t5, -0.5f, -0.5f);
                        const float aC   = X - WD;
                        const float t4   = tanh_fast(aC);
                        const float hC   = -0.5f * aC;           // 0.5(WD-X)
                        const float mC   = fmaf(0.5f, WD, 0.5f * X);
                        const float ET33 = fmaf(t4, hC, mC);     // chain: 28cyc
                        const float WDD  = WD + D2;
                        const float WDn  = fmaf(ng5, ET33, WDD); // WD + D2 - ET3
                        const float v    = WDn * invW10;         // wd/W (new)
                        const float bv   = negb2 * v;
                        const float dd   = fmaf(bv, v, ct2);     // p - s
                        const float tq   = tanh_fast(10.0f * dd);
                        const float qh   = halfF * dd;
                        qv[i] = fmaf(tq, qh, qh);                // F*H(p-s)*(p-s)
                        WD = WDn;
                    }
                    out4[kc * NGRP_C + j] =
                        make_float4(qv[0], qv[1], qv[2], qv[3]);
                }
            }
        }
        __syncthreads();
    }
}

extern "C" void kernel_launch(void* const* d_in, const int* in_sizes, int n_in,
                              void* d_out, int out_size) {
    const float* inputs = (const float*)d_in[0];
    const float* wum = (const float*)d_in[1];
    const float* wlm = (const float*)d_in[2];
    const float* wdm = (const float*)d_in[3];
    const float* c   = (const float*)d_in[4];
    const float* bb  = (const float*)d_in[5];
    const float* k1  = (const float*)d_in[6];
    const float* k2  = (const float*)d_in[7];
    const float* k3  = (const float*)d_in[8];
    float* out = (float*)d_out;

    const int B = in_sizes[0] / (T_LEN * 3);

    dim3 block(96);                 // 3 warps: A, B, C stages
    dim3 grid(B / 32);              // 32 rows per block
    xaj_kernel<<<grid, block>>>(inputs, wum, wlm, wdm, c, bb, k1, k2, k3, out, B);
}

// round 6
// speedup vs baseline: 2.0309x; 1.4518x over previous
#include <cuda_runtime.h>

#define T_LEN   2048
#define CSTEP   16                      // timesteps per chunk
#define NCHUNK  (T_LEN / CSTEP)         // 128
#define NITER   (NCHUNK + 3)            // 4-deep pipeline: L -> A -> B -> C
#define NGRP_C  (CSTEP / 4)             // float4-groups per chunk (4)

__device__ __forceinline__ float tanh_fast(float x) {
    float y;
    asm("tanh.approx.f32 %0, %1;" : "=f"(y) : "f"(x));
    return y;
}

// State carried in the x10 domain (WU = 10*wu etc); clips at +-1e5 are exact
// no-ops on reachable values (|state| <= O(T) ~ 2e3).
//
// 4-warp pipeline, skewed by one chunk per stage:
//   warp3 (L): STS chunk k (preloaded into regs at iter k-1), LDG chunk k+1
//   warp0 (A): WU chain  on chunk k-1 -> REM, D1, ct2 = p - c2*(wu/W)^2
//   warp1 (B): WL chain  on chunk k-2 -> X, D2
//   warp2 (C): WD chain  on chunk k-3 -> q, global stores
// One __syncthreads per iteration. Loader LDGs are issued one full iteration
// before their STS, so DRAM latency never sits behind the barrier.
// smem: 6 x 2x16x32x4 (24KB) + sCT 3x16x32x4 (6KB) = 30KB static (< 48KB).
__global__ void __launch_bounds__(128, 1) xaj_kernel(
    const float* __restrict__ inputs,
    const float* __restrict__ pwum, const float* __restrict__ pwlm,
    const float* __restrict__ pwdm, const float* __restrict__ pc,
    const float* __restrict__ pb,  const float* __restrict__ pk1,
    const float* __restrict__ pk2, const float* __restrict__ pk3,
    float* __restrict__ out, int B)
{
    __shared__ float sPET[2][CSTEP][32];
    __shared__ float sP  [2][CSTEP][32];
    __shared__ float sREM[2][CSTEP][32];
    __shared__ float sD1 [2][CSTEP][32];
    __shared__ float sX  [2][CSTEP][32];
    __shared__ float sD2 [2][CSTEP][32];
    __shared__ float sCT [3][CSTEP][32];   // ct2 travels A -> C (distance 2)

    const int lane = threadIdx.x & 31;
    const int wid  = threadIdx.x >> 5;
    const int row  = blockIdx.x * 32 + lane;

    // scalar params (reference arg swap: runoff_production(wu, wd, wl, p,
    // wum, wdm, wlm, b, c))
    const float wum_p = pwum[0] * 19.9f + 0.1f;
    const float wlm_p = pwdm[0] * 30.0f + 60.0f;
    const float wdm_p = pwlm[0] * 60.0f + 60.0f;
    const float W      = wum_p + wlm_p + wdm_p;
    const float invW10 = 0.1f / W;           // x10-state -> w/W
    const float negc2  = -(pc[0] * 0.19f + 0.01f);
    const float negb2  = -(pb[0] * 0.30f + 0.10f);
    const float k1 = pk1[0] * 0.69f + 0.01f;
    const float k2 = pk2[0] * 0.69f + 0.01f;
    const float k3 = pk3[0] * 0.89f + 0.01f;
    const float F  = k1 + 0.5f * k2 * (1.0f - k1)
                   + 0.25f * k3 * (1.0f - k2) * (1.0f - k1);
    const float halfF = 0.5f * F;

    const float4* __restrict__ in4 =
        reinterpret_cast<const float4*>(inputs + (size_t)row * (T_LEN * 3));
    float4* __restrict__ out4 =
        reinterpret_cast<float4*>(out + (size_t)row * T_LEN);

    float WU = 0.0f, WL = 0.0f, WD = 0.0f;

    // loader's in-flight chunk registers (chunk to be STS'd this iteration)
    float4 f[NGRP_C][3];
    if (wid == 3) {
        #pragma unroll
        for (int j = 0; j < NGRP_C; ++j) {
            f[j][0] = in4[j * 3 + 0];
            f[j][1] = in4[j * 3 + 1];
            f[j][2] = in4[j * 3 + 2];
        }
    }

    for (int k = 0; k < NITER; ++k) {
        if (wid == 3) {
            // ---- loader: STS chunk k, then issue LDGs for chunk k+1 ----
            if (k < NCHUNK) {
                const int slot = k & 1;
                #pragma unroll
                for (int j = 0; j < NGRP_C; ++j) {
                    // (B,T,3): pet = ch0, p = ch2
                    const float pet_[4] = { f[j][0].x, f[j][0].w,
                                            f[j][1].z, f[j][2].y };
                    const float pr_ [4] = { f[j][0].z, f[j][1].y,
                                            f[j][2].x, f[j][2].w };
                    #pragma unroll
                    for (int i = 0; i < 4; ++i) {
                        sPET[slot][j * 4 + i][lane] = 10.0f * pet_[i];
                        sP  [slot][j * 4 + i][lane] = 10.0f * pr_[i];
                    }
                }
                if (k + 1 < NCHUNK) {
                    #pragma unroll
                    for (int j = 0; j < NGRP_C; ++j) {
                        const int g = (k + 1) * NGRP_C + j;
                        f[j][0] = in4[g * 3 + 0];
                        f[j][1] = in4[g * 3 + 1];
                        f[j][2] = in4[g * 3 + 2];
                    }
                }
            }
        } else if (wid == 0) {
            // ---- stage A: WU chain, chunk k-1 ----
            if (k >= 1 && k <= NCHUNK) {
                const int ka = k - 1, slot = ka & 1, cslot = ka % 3;
                #pragma unroll 4
                for (int t = 0; t < CSTEP; ++t) {
                    const float pet10 = sPET[slot][t][lane];
                    const float p10   = sP  [slot][t][lane];
                    const float a    = WU - pet10;
                    const float ha   = 0.5f * a;
                    const float ct   = fmaf(-0.5f, pet10, p10);
                    const float base = fmaf(0.5f, WU, ct);
                    const float sum  = WU + p10;
                    const float t1   = tanh_fast(a);
                    const float WUn  = fmaf(t1, ha, base);   // carried: ~24cyc
                    const float ET1  = sum - WUn;            // off-chain
                    const float Z    = pet10 - ET1;
                    const float tr   = tanh_fast(Z);
                    const float hZ   = 0.5f * Z;
                    const float REM  = fmaf(tr, hZ, hZ);
                    const float D1   = p10 - ET1;
                    const float u    = WUn * invW10;         // wu/W (new state)
                    const float cu   = negc2 * u;
                    const float praw = 0.1f * p10;
                    const float ct2  = fmaf(cu, u, praw);    // p - c2*u^2
                    sREM[slot][t][lane]  = REM;
                    sD1 [slot][t][lane]  = D1;
                    sCT [cslot][t][lane] = ct2;
                    WU = WUn;
                }
            }
        } else if (wid == 1) {
            // ---- stage B: WL chain, chunk k-2 ----
            if (k >= 2 && k <= NCHUNK + 1) {
                const int kb = k - 2, slot = kb & 1;
                #pragma unroll 4
                for (int t = 0; t < CSTEP; ++t) {
                    const float REM  = sREM[slot][t][lane];
                    const float D1   = sD1 [slot][t][lane];
                    const float t3   = tanh_fast(REM);           // gate H(rem)
                    const float g3   = fmaf(t3,  0.5f,  0.5f);
                    const float ng3  = fmaf(t3, -0.5f, -0.5f);
                    const float aB   = REM - WL;
                    const float t2   = tanh_fast(aB);
                    const float hB   = -0.5f * aB;               // 0.5(WL-REM)
                    const float mB   = fmaf(0.5f, WL, 0.5f * REM);
                    const float ET22 = fmaf(t2, hB, mB);         // carried: 28cyc
                    const float ET2  = g3 * ET22;
                    const float WLD  = WL + D1;
                    WL = fmaf(ng3, ET22, WLD);                   // WL + D1 - ET2
                    sX [slot][t][lane] = REM - ET2;
                    sD2[slot][t][lane] = D1  - ET2;
                }
            }
        } else {
            // ---- stage C: WD chain + runoff/q, chunk k-3 ----
            if (k >= 3) {
                const int kc = k - 3, slot = kc & 1, cslot = kc % 3;
                #pragma unroll
                for (int j = 0; j < NGRP_C; ++j) {
                    float qv[4];
                    #pragma unroll
                    for (int i = 0; i < 4; ++i) {
                        const int   t    = j * 4 + i;
                        const float X    = sX [slot][t][lane];
                        const float D2   = sD2[slot][t][lane];
                        const float ct2  = sCT[cslot][t][lane];
                        const float t5   = tanh_fast(X);         // gate H(x)
                        const float ng5  = fmaf(t5, -0.5f, -0.5f);
                        const float aC   = X - WD;
                        const float t4   = tanh_fast(aC);
                        const float hC   = -0.5f * aC;           // 0.5(WD-X)
                        const float mC   = fmaf(0.5f, WD, 0.5f * X);
                        const float ET33 = fmaf(t4, hC, mC);     // carried: 28cyc
                        const float WDD  = WD + D2;
                        const float WDn  = fmaf(ng5, ET33, WDD); // WD + D2 - ET3
                        const float v    = WDn * invW10;         // wd/W (new)
                        const float bv   = negb2 * v;
                        const float dd   = fmaf(bv, v, ct2);     // p - s
                        const float tq   = tanh_fast(10.0f * dd);
                        const float qh   = halfF * dd;
                        qv[i] = fmaf(tq, qh, qh);                // F*H(p-s)*(p-s)
                        WD = WDn;
                    }
                    out4[kc * NGRP_C + j] =
                        make_float4(qv[0], qv[1], qv[2], qv[3]);
                }
            }
        }
        __syncthreads();
    }
}

extern "C" void kernel_launch(void* const* d_in, const int* in_sizes, int n_in,
                              void* d_out, int out_size) {
    const float* inputs = (const float*)d_in[0];
    const float* wum = (const float*)d_in[1];
    const float* wlm = (const float*)d_in[2];
    const float* wdm = (const float*)d_in[3];
    const float* c   = (const float*)d_in[4];
    const float* bb  = (const float*)d_in[5];
    const float* k1  = (const float*)d_in[6];
    const float* k2  = (const float*)d_in[7];
    const float* k3  = (const float*)d_in[8];
    float* out = (float*)d_out;

    const int B = in_sizes[0] / (T_LEN * 3);

    dim3 block(128);                // 4 warps: A, B, C, Loader
    dim3 grid(B / 32);              // 32 rows per block
    xaj_kernel<<<grid, block>>>(inputs, wum, wlm, wdm, c, bb, k1, k2, k3, out, B);
}